// round 6
// baseline (speedup 1.0000x reference)
#include <cuda_runtime.h>
#include <math.h>

#define B_ 2048
#define F_ 512
#define H_ 256
#define E_ 64
#define K_ 8

// Packed fp32x2 helpers (sm_103a). Element-wise rn FMA: bitwise identical to
// two scalar FFMAs, 2x fma-pipe throughput.
#define PACKF2(out, lo, hi) \
    asm("mov.b64 %0, {%1, %2};" : "=l"(out) : "f"(lo), "f"(hi))
#define FMAF2(acc, a, b) \
    asm("fma.rn.f32x2 %0, %1, %2, %0;" : "+l"(acc) : "l"(a), "l"(b))
#define UNPACKF2(lo, hi, in) \
    asm("mov.b64 {%0, %1}, %2;" : "=f"(lo), "=f"(hi) : "l"(in))

// ------------------------- device scratch (no allocs allowed) ---------------
__device__ float g_M[F_ * E_];        // [f][e] combined gate matrix (incl 1/16)
__device__ float g_c[E_];             // bias term
__device__ float g_enT[F_ * E_];      // [f][e] normalized expert features
__device__ float g_t[E_];             // trust * staleness
__device__ float g_score[B_ * E_];
__device__ float g_w[B_ * K_];        // softmax weights per (b,k)
__device__ int   g_cnt[E_];
__device__ int   g_list[E_ * B_];     // per-expert row list, entry = b*8+k
__device__ float g_partial[(size_t)B_ * K_ * F_];  // 32 MB

// ------------------------- prologue: expert-side precompute ------------------
__global__ void prep_expert_kernel(const float* __restrict__ ef,
                                   const float* __restrict__ trust,
                                   const float* __restrict__ dt,
                                   const float* __restrict__ proj_b,
                                   const float* __restrict__ emb) {
    int e = blockIdx.x;
    int t = threadIdx.x;  // 128
    __shared__ float red[128];

    float s = 0.f;
    for (int f = t; f < F_; f += 128) { float v = ef[e * F_ + f]; s += v * v; }
    red[t] = s; __syncthreads();
    for (int o = 64; o > 0; o >>= 1) { if (t < o) red[t] += red[t + o]; __syncthreads(); }
    float denom = fmaxf(sqrtf(red[0]), 1e-8f);
    for (int f = t; f < F_; f += 128) g_enT[f * E_ + e] = ef[e * F_ + f] / denom;

    float s2 = 0.f;
    for (int h = t; h < H_; h += 128) s2 += proj_b[h] * emb[e * H_ + h];
    __syncthreads(); red[t] = s2; __syncthreads();
    for (int o = 64; o > 0; o >>= 1) { if (t < o) red[t] += red[t + o]; __syncthreads(); }
    if (t == 0) {
        g_c[e] = red[0] * 0.0625f;
        g_t[e] = trust[e] * fmaxf(0.1f, expf(-0.005f * dt[e]));
        g_cnt[e] = 0;
    }
}

// M[f][e] = sum_h proj_w[h][f] * emb[e][h] / 16
__global__ void prep_M_kernel(const float* __restrict__ pw,
                              const float* __restrict__ emb) {
    int t = threadIdx.x;          // 256
    int fi = t >> 6;              // 0..3
    int e = t & 63;
    int fbase = blockIdx.x * 4;
    __shared__ float sPw[64][4];
    float acc = 0.f;
    for (int h0 = 0; h0 < H_; h0 += 64) {
        __syncthreads();
        sPw[t >> 2][t & 3] = pw[(h0 + (t >> 2)) * F_ + fbase + (t & 3)];
        __syncthreads();
        #pragma unroll 8
        for (int hl = 0; hl < 64; hl++)
            acc += sPw[hl][fi] * emb[e * H_ + h0 + hl];
    }
    g_M[(fbase + fi) * E_ + e] = acc * 0.0625f;
}

// ------------------------- scores: gate * sim * t ----------------------------
// Thread r = row (16/block), el = expert quad (4 consecutive experts).
__global__ void __launch_bounds__(256) score_kernel(const float* __restrict__ feat) {
    int b0 = blockIdx.x * 16;
    __shared__ float sx[16][F_];
    __shared__ float snorm[16];
    int t = threadIdx.x;  // 256

    for (int i = t; i < 16 * F_ / 4; i += 256)
        *(float4*)&sx[i >> 7][(i & 127) << 2] =
            *(const float4*)&feat[(size_t)(b0 + (i >> 7)) * F_ + ((i & 127) << 2)];
    __syncthreads();

    int warp = t >> 5, lane = t & 31;
    for (int rr = 0; rr < 2; rr++) {
        int r = warp * 2 + rr;
        float s = 0.f;
        for (int f = lane; f < F_; f += 32) { float v = sx[r][f]; s += v * v; }
        for (int o = 16; o; o >>= 1) s += __shfl_xor_sync(0xffffffffu, s, o);
        if (lane == 0) snorm[r] = sqrtf(s);
    }
    __syncthreads();

    int r = t >> 4;            // 0..15
    int el = t & 15;           // expert quad -> experts 4*el .. 4*el+3
    float inv = 1.0f / fmaxf(snorm[r], 1e-8f);
    const float4* M4 = (const float4*)g_M;
    const float4* E4 = (const float4*)g_enT;
    float4 s1 = {0, 0, 0, 0}, s2 = {0, 0, 0, 0};
    #pragma unroll 4
    for (int f = 0; f < F_; f++) {
        float x = sx[r][f];
        float4 m = M4[f * 16 + el];
        float4 en = E4[f * 16 + el];
        s1.x += x * m.x;  s1.y += x * m.y;  s1.z += x * m.z;  s1.w += x * m.w;
        s2.x += x * en.x; s2.y += x * en.y; s2.z += x * en.z; s2.w += x * en.w;
    }
    float sv1[4] = {s1.x, s1.y, s1.z, s1.w};
    float sv2[4] = {s2.x, s2.y, s2.z, s2.w};
    #pragma unroll
    for (int j = 0; j < 4; j++) {
        int e = 4 * el + j;
        float gate = 1.0f / (1.0f + expf(-(sv1[j] + g_c[e])));
        float sim = fmaxf(sv2[j], 0.0f) * inv;
        g_score[(size_t)(b0 + r) * E_ + e] = gate * sim * g_t[e];
    }
}

// ------------------------- top-8 + softmax + bucket --------------------------
__global__ void topk_kernel() {
    int warp = threadIdx.x >> 5, lane = threadIdx.x & 31;
    int b = blockIdx.x * 8 + warp;
    float v0 = g_score[b * E_ + lane];
    float v1 = g_score[b * E_ + 32 + lane];

    float selv[K_]; int seli[K_];
    #pragma unroll
    for (int k = 0; k < K_; k++) {
        float bv; int bi;
        if (v0 >= v1) { bv = v0; bi = lane; } else { bv = v1; bi = lane + 32; }
        for (int o = 16; o; o >>= 1) {
            float ov = __shfl_xor_sync(0xffffffffu, bv, o);
            int oi = __shfl_xor_sync(0xffffffffu, bi, o);
            if (ov > bv || (ov == bv && oi < bi)) { bv = ov; bi = oi; }
        }
        selv[k] = bv; seli[k] = bi;
        if (bi == lane) v0 = -1.0f;
        else if (bi == lane + 32) v1 = -1.0f;
    }
    float m = selv[0];
    float ex[K_], sum = 0.f;
    #pragma unroll
    for (int k = 0; k < K_; k++) { ex[k] = expf(selv[k] - m); sum += ex[k]; }
    float rs = 1.0f / sum;
    if (lane < K_) {
        int k = lane;
        int entry = b * K_ + k;
        g_w[entry] = ex[k] * rs;
        int e = seli[k];
        int pos = atomicAdd(&g_cnt[e], 1);
        g_list[e * B_ + pos] = entry;
    }
}

// ------------------------- grouped expert GEMM (double-buffered, f32x2) ------
// Per expert e: Y[rows, 512] = X[rows, 512] @ W_e[512, 512]; writes w*(Y+bias)
// into g_partial[entry]. Tile 64x64, TK=16, 256 threads, 4x4 frag, 2-stage smem.
// Inner product in packed fma.rn.f32x2: acc pairs along i (A-fragment pairs
// come free from the float4), B values duplicated per j.
__global__ void __launch_bounds__(256) gemm_kernel(const float* __restrict__ feat,
                                                   const float* __restrict__ fw,
                                                   const float* __restrict__ fb) {
    int e = blockIdx.z;
    int ne = g_cnt[e];
    int m0 = blockIdx.x * 64;
    if (m0 >= ne) return;
    int n0 = blockIdx.y * 64;

    __shared__ float sX[2][16][68];
    __shared__ float sW[2][16][64];
    __shared__ int sEntry[64];

    int t = threadIdx.x;
    if (t < 64) sEntry[t] = (m0 + t < ne) ? g_list[e * B_ + m0 + t] : -1;
    __syncthreads();

    int xm = t >> 2, xk = (t & 3) << 2;
    int xent = sEntry[xm];
    const float* xrow = feat + (size_t)(xent >= 0 ? (xent >> 3) : 0) * F_;
    int wk = t >> 4, wf = (t & 15) << 2;
    const float* wptr = fw + ((size_t)e * F_ + wk) * F_ + n0 + wf;
    int tm = t >> 4, tn = t & 15;

    // Preload tile 0 into buffer 0.
    {
        float4 xv = *(const float4*)(xrow + xk);
        float4 wv = *(const float4*)(wptr);
        sX[0][xk + 0][xm] = xv.x; sX[0][xk + 1][xm] = xv.y;
        sX[0][xk + 2][xm] = xv.z; sX[0][xk + 3][xm] = xv.w;
        *(float4*)&sW[0][wk][wf] = wv;
    }
    __syncthreads();

    // accp[ip][j] = ( acc[2*ip][j] , acc[2*ip+1][j] ) packed f32x2
    unsigned long long accp[2][4] = {};
    int buf = 0;
    for (int k0 = 0; k0 < F_; k0 += 16) {
        bool has_next = (k0 + 16) < F_;
        float4 nxv, nwv;
        if (has_next) {
            nxv = *(const float4*)(xrow + k0 + 16 + xk);
            nwv = *(const float4*)(wptr + (size_t)(k0 + 16) * F_);
        }
        #pragma unroll
        for (int k = 0; k < 16; k++) {
            float4 a = *(float4*)&sX[buf][k][tm << 2];
            float4 bb = *(float4*)&sW[buf][k][tn << 2];
            unsigned long long ap0, ap1;
            PACKF2(ap0, a.x, a.y);
            PACKF2(ap1, a.z, a.w);
            unsigned long long bd0, bd1, bd2, bd3;
            PACKF2(bd0, bb.x, bb.x);
            PACKF2(bd1, bb.y, bb.y);
            PACKF2(bd2, bb.z, bb.z);
            PACKF2(bd3, bb.w, bb.w);
            FMAF2(accp[0][0], ap0, bd0); FMAF2(accp[0][1], ap0, bd1);
            FMAF2(accp[0][2], ap0, bd2); FMAF2(accp[0][3], ap0, bd3);
            FMAF2(accp[1][0], ap1, bd0); FMAF2(accp[1][1], ap1, bd1);
            FMAF2(accp[1][2], ap1, bd2); FMAF2(accp[1][3], ap1, bd3);
        }
        if (has_next) {
            int nb = buf ^ 1;
            sX[nb][xk + 0][xm] = nxv.x; sX[nb][xk + 1][xm] = nxv.y;
            sX[nb][xk + 2][xm] = nxv.z; sX[nb][xk + 3][xm] = nxv.w;
            *(float4*)&sW[nb][wk][wf] = nwv;
            __syncthreads();
            buf = nb;
        }
    }

    // Unpack to scalar acc[4][4].
    float acc[4][4];
    #pragma unroll
    for (int ip = 0; ip < 2; ip++)
        #pragma unroll
        for (int j = 0; j < 4; j++)
            UNPACKF2(acc[2 * ip][j], acc[2 * ip + 1][j], accp[ip][j]);

    float4 bias = *(const float4*)(fb + (size_t)e * F_ + n0 + (tn << 2));
    #pragma unroll
    for (int i = 0; i < 4; i++) {
        int entry = sEntry[(tm << 2) + i];
        if (entry >= 0) {
            float wgt = g_w[entry];
            float4 o;
            o.x = wgt * (acc[i][0] + bias.x);
            o.y = wgt * (acc[i][1] + bias.y);
            o.z = wgt * (acc[i][2] + bias.z);
            o.w = wgt * (acc[i][3] + bias.w);
            *(float4*)(g_partial + (size_t)entry * F_ + n0 + (tn << 2)) = o;
        }
    }
}

// ------------------------- final reduce over K slots -------------------------
__global__ void reduce_kernel(float4* __restrict__ out) {
    int i = blockIdx.x * 256 + threadIdx.x;   // over B*F/4 = 262144
    const float4* p = (const float4*)g_partial;
    int b = i >> 7;        // F/4 = 128 float4 per row
    int f4 = i & 127;
    float4 s = {0.f, 0.f, 0.f, 0.f};
    #pragma unroll
    for (int k = 0; k < K_; k++) {
        float4 v = p[(size_t)(b * K_ + k) * 128 + f4];
        s.x += v.x; s.y += v.y; s.z += v.z; s.w += v.w;
    }
    out[i] = s;
}

// ------------------------- launch ------------------------------------------
extern "C" void kernel_launch(void* const* d_in, const int* in_sizes, int n_in,
                              void* d_out, int out_size) {
    const float* features  = (const float*)d_in[0];
    const float* proj_w    = (const float*)d_in[1];
    const float* proj_b    = (const float*)d_in[2];
    const float* emb       = (const float*)d_in[3];
    const float* ef        = (const float*)d_in[4];
    const float* trust     = (const float*)d_in[5];
    const float* dt        = (const float*)d_in[6];
    const float* fst_w     = (const float*)d_in[7];
    const float* fst_b     = (const float*)d_in[8];
    float* out = (float*)d_out;

    prep_expert_kernel<<<E_, 128>>>(ef, trust, dt, proj_b, emb);
    prep_M_kernel<<<F_ / 4, 256>>>(proj_w, emb);
    score_kernel<<<B_ / 16, 256>>>(features);
    topk_kernel<<<B_ / 8, 256>>>();
    gemm_kernel<<<dim3(B_ / 64, F_ / 64, E_), 256>>>(features, fst_w, fst_b);
    reduce_kernel<<<(B_ * F_ / 4) / 256, 256>>>((float4*)out);
}